// round 1
// baseline (speedup 1.0000x reference)
#include <cuda_runtime.h>
#include <cuda_bf16.h>

// Tree constants: BRANCH=8, DEPTH=4
// level sizes: 1, 8, 64, 512, 4096 ; offsets: 0, 1, 9, 73, 585, 4681
#define E_TOTAL   4681
#define N_INTERN  585     // nodes with children (levels 0..3)
#define NTHREADS  512

__global__ __launch_bounds__(NTHREADS, 4)
void softmax_cascade_kernel(const float* __restrict__ x,
                            float* __restrict__ out)
{
    const int row = blockIdx.x;
    const float* __restrict__ xr  = x   + (size_t)row * E_TOTAL;
    float* __restrict__       outr = out + (size_t)row * E_TOTAL;

    __shared__ float prob[N_INTERN];  // probs of levels 0..3 (parents)

    const int t    = threadIdx.x;
    const int lane = t & 31;

    // ---------------- Level 1: children 1..8 (parent = root, prob 1) ------
    if (t < 32) {
        const int c = 1 + (lane & 7);
        float e = __expf(xr[c]);
        float s = e;
        s += __shfl_xor_sync(0xffffffffu, s, 1);
        s += __shfl_xor_sync(0xffffffffu, s, 2);
        s += __shfl_xor_sync(0xffffffffu, s, 4);
        const float p = __fdividef(e, s);
        if (lane < 8) { prob[c] = p; outr[c] = p; }
        if (lane == 8) { prob[0] = 1.0f; outr[0] = 1.0f; }
    }
    __syncthreads();

    // ---------------- Level 2: children 9..72 (parents 1..8) --------------
    if (t < 64) {
        const int c   = 9 + t;
        const int par = 1 + (t >> 3);
        float e = __expf(xr[c]);
        float s = e;
        s += __shfl_xor_sync(0xffffffffu, s, 1);
        s += __shfl_xor_sync(0xffffffffu, s, 2);
        s += __shfl_xor_sync(0xffffffffu, s, 4);
        const float p = __fdividef(e, s) * prob[par];
        prob[c] = p;
        outr[c] = p;
    }
    __syncthreads();

    // ---------------- Level 3: children 73..584 (parents 9..72) -----------
    {
        const int c   = 73 + t;
        const int par = 9 + (t >> 3);
        float e = __expf(xr[c]);
        float s = e;
        s += __shfl_xor_sync(0xffffffffu, s, 1);
        s += __shfl_xor_sync(0xffffffffu, s, 2);
        s += __shfl_xor_sync(0xffffffffu, s, 4);
        const float p = __fdividef(e, s) * prob[par];
        prob[c] = p;
        outr[c] = p;
    }
    __syncthreads();

    // ---------------- Level 4: children 585..4680 (parents 73..584) -------
    // 4096 leaves, 8 iterations of 512 threads. Groups of 8 consecutive
    // leaves live on 8 aligned consecutive lanes -> shfl.bfly masks 1,2,4.
#pragma unroll
    for (int i = 0; i < 8; ++i) {
        const int idx = i * NTHREADS + t;       // 0..4095
        const int c   = 585 + idx;
        const int par = 73 + (idx >> 3);
        float e = __expf(xr[c]);
        float s = e;
        s += __shfl_xor_sync(0xffffffffu, s, 1);
        s += __shfl_xor_sync(0xffffffffu, s, 2);
        s += __shfl_xor_sync(0xffffffffu, s, 4);
        outr[c] = __fdividef(e, s) * prob[par];
    }
}

extern "C" void kernel_launch(void* const* d_in, const int* in_sizes, int n_in,
                              void* d_out, int out_size)
{
    const float* x = (const float*)d_in[0];   // inputs [B, E] fp32
    // d_in[1] = segment_ids, d_in[2] = path_onehot -- structure is static,
    // baked into the kernel.
    float* out = (float*)d_out;

    const int batch = in_sizes[0] / E_TOTAL;  // 8192
    softmax_cascade_kernel<<<batch, NTHREADS>>>(x, out);
}

// round 6
// speedup vs baseline: 1.1918x; 1.1918x over previous
#include <cuda_runtime.h>
#include <cuda_bf16.h>

// Tree: BRANCH=8, DEPTH=4. Level sizes 1,8,64,512,4096; offsets 0,1,9,73,585,4681.
// parent(c) = (c-1)>>3 for all c >= 1.
#define E_TOTAL   4681
#define NT        512

__global__ __launch_bounds__(NT, 3)
void softmax_cascade_kernel(const float* __restrict__ x,
                            float* __restrict__ out)
{
    const int row = blockIdx.x;
    const float* __restrict__ xr   = x   + (size_t)row * E_TOTAL;
    float* __restrict__       outr = out + (size_t)row * E_TOTAL;

    __shared__ float rs[585];    // softmax ratio per internal node (node id index)
    __shared__ float ps3[512];   // cumulative path prob of level-3 node (73+i)

    const int t = threadIdx.x;

    // ------------- issue ALL gmem loads up front (10 independent LDGs) ----
    float xa = xr[1 + t];                                // nodes 1..512
    float xb = (t < 72) ? xr[513 + t] : 0.0f;            // nodes 513..584
    float lx[8];                                         // leaves
#pragma unroll
    for (int i = 0; i < 8; ++i)
        lx[i] = xr[585 + i * NT + t];

    // ------------- Phase A: per-group softmax ratios, ALL levels at once --
    // Thread t handles node c = t+1; every 8-child group is 8-aligned in t.
    {
        float e = __expf(xa);
        float s = e;
        s += __shfl_xor_sync(0xffffffffu, s, 1);
        s += __shfl_xor_sync(0xffffffffu, s, 2);
        s += __shfl_xor_sync(0xffffffffu, s, 4);
        rs[1 + t] = __fdividef(e, s);
    }
    if (t < 128) {   // warps 0-3 fully active -> full-mask shfl is safe
        float e = __expf(xb);
        float s = e;
        s += __shfl_xor_sync(0xffffffffu, s, 1);
        s += __shfl_xor_sync(0xffffffffu, s, 2);
        s += __shfl_xor_sync(0xffffffffu, s, 4);
        if (t < 72) rs[513 + t] = __fdividef(e, s);
    }
    __syncthreads();

    // ------------- Phase B: path products (depth <= 3, no chaining) -------
    {
        const int c  = 73 + t;          // level-3 node
        const int p2 = (c - 1) >> 3;    // level-2 parent (9..72)
        const int p1 = (p2 - 1) >> 3;   // level-1 ancestor (1..8)
        const float p = rs[c] * rs[p2] * rs[p1];
        ps3[t]  = p;
        outr[c] = p;
    }
    if (t < 73) {
        if (t == 72) {
            outr[0] = 1.0f;             // root
        } else {
            const int c = 1 + t;        // levels 1..2
            float p = rs[c];
            if (c >= 9) p *= rs[(c - 1) >> 3];
            outr[c] = p;
        }
    }
    __syncthreads();

    // ------------- Leaves: x already in registers -------------------------
#pragma unroll
    for (int i = 0; i < 8; ++i) {
        const int idx = i * NT + t;     // 0..4095
        float e = __expf(lx[i]);
        float s = e;
        s += __shfl_xor_sync(0xffffffffu, s, 1);
        s += __shfl_xor_sync(0xffffffffu, s, 2);
        s += __shfl_xor_sync(0xffffffffu, s, 4);
        outr[585 + idx] = __fdividef(e, s) * ps3[idx >> 3];
    }
}

extern "C" void kernel_launch(void* const* d_in, const int* in_sizes, int n_in,
                              void* d_out, int out_size)
{
    const float* x = (const float*)d_in[0];   // inputs [B, E] fp32
    float* out = (float*)d_out;
    const int batch = in_sizes[0] / E_TOTAL;  // 8192
    softmax_cascade_kernel<<<batch, NT>>>(x, out);
}